// round 2
// baseline (speedup 1.0000x reference)
#include <cuda_runtime.h>
#include <cstdint>

// Problem constants
namespace {
constexpr int NB = 8;
constexpr int NQ = 500;
constexpr int NC = 256;   // channels
constexpr int NS = 8;     // sampling points along polynomial
constexpr float SSCALE = 0.077f;
}

__constant__ int c_hw[4] = {80, 40, 20, 10};          // square levels
__constant__ int c_st[4] = {0, 6400, 8000, 8400};

__device__ __forceinline__ float tanh_fast(float x) {
    float r;
    asm("tanh.approx.f32 %0, %1;" : "=f"(r) : "f"(x));
    return r;
}
__device__ __forceinline__ uint64_t pack2(float v) {
    uint64_t r;
    asm("mov.b64 %0, {%1, %1};" : "=l"(r) : "r"(__float_as_uint(v)));
    return r;
}
__device__ __forceinline__ void ffma2(uint64_t& d, uint64_t a, uint64_t b) {
    // d = a * b + d  (packed f32x2 — Blackwell dual-FMA, PTX-only path)
    asm("fma.rn.f32x2 %0, %1, %2, %0;" : "+l"(d) : "l"(a), "l"(b));
}
__device__ __forceinline__ float2 unpack2(uint64_t v) {
    float2 f;
    asm("mov.b64 {%0, %1}, %2;" : "=f"(f.x), "=f"(f.y) : "l"(v));
    return f;
}

__global__ __launch_bounds__(256) void decoder_kernel(
    const float* __restrict__ ref_polys,   // (B,Q,8)
    const int*   __restrict__ ref_levels,  // (B,Q)
    const float* __restrict__ memory,      // (B,8500,256)
    const float* __restrict__ W1,          // (256,256)
    const float* __restrict__ b1,          // (256,)
    const float* __restrict__ W2,          // (256,4)
    const float* __restrict__ b2,          // (4,)
    float*       __restrict__ out)         // (B,Q,16,2)
{
    __shared__ float pts[NS * 2];        // (s, xy) sampling points in [-1,1]
    __shared__ float emb[NC * NS];       // [c][s]
    __shared__ float hsm[NC * NS];       // [j][s]
    __shared__ float w2s[NC * 4];        // W2 staged

    const int bq  = blockIdx.x;          // b*Q + q
    const int tid = threadIdx.x;
    const int b   = bq / NQ;

    // ---- Stage 1: polynomial eval -> sampling points ----
    if (tid < NS) {
        const float lam = tid * (1.0f / 7.0f);
        const float* rp = ref_polys + bq * 8;
        float px = ((rp[0] * lam + rp[1]) * lam + rp[2]) * lam + rp[3];
        float py = ((rp[4] * lam + rp[5]) * lam + rp[6]) * lam + rp[7];
        pts[tid * 2 + 0] = 2.0f * (px - 0.5f);
        pts[tid * 2 + 1] = 2.0f * (py - 0.5f);
    }
    __syncthreads();

    // Stage W2 into smem while doing the gather
    ((float4*)w2s)[tid] = ((const float4*)W2)[tid];

    // ---- Stage 2: bilinear gather (thread = channel) ----
    const int lvl = ref_levels[bq];
    const int ww  = c_hw[lvl];
    const int hh  = ww;
    const float* mem = memory + ((size_t)b * 8500 + c_st[lvl]) * NC + tid;

    float e[NS];
#pragma unroll
    for (int s = 0; s < NS; ++s) {
        const float sx = pts[s * 2 + 0];
        const float sy = pts[s * 2 + 1];
        const float gx = (sx + 1.0f) * 0.5f * (float)ww - 0.5f;
        const float gy = (sy + 1.0f) * 0.5f * (float)hh - 0.5f;
        const float x0f = floorf(gx), y0f = floorf(gy);
        const float wx1 = gx - x0f, wy1 = gy - y0f;
        const float wx0 = 1.0f - wx1, wy0 = 1.0f - wy1;
        const int x0 = (int)x0f, y0 = (int)y0f;
        const bool vx0 = (x0 >= 0) && (x0 < ww);
        const bool vx1 = (x0 >= -1) && (x0 < ww - 1);
        const bool vy0 = (y0 >= 0) && (y0 < hh);
        const bool vy1 = (y0 >= -1) && (y0 < hh - 1);
        const int x0c = min(max(x0, 0), ww - 1);
        const int x1c = min(max(x0 + 1, 0), ww - 1);
        const int y0c = min(max(y0, 0), hh - 1);
        const int y1c = min(max(y0 + 1, 0), hh - 1);
        const float w00 = (vx0 && vy0) ? wy0 * wx0 : 0.0f;
        const float w01 = (vx1 && vy0) ? wy0 * wx1 : 0.0f;
        const float w10 = (vx0 && vy1) ? wy1 * wx0 : 0.0f;
        const float w11 = (vx1 && vy1) ? wy1 * wx1 : 0.0f;
        float acc;
        acc  = w00 * __ldg(mem + (y0c * ww + x0c) * NC);
        acc += w01 * __ldg(mem + (y0c * ww + x1c) * NC);
        acc += w10 * __ldg(mem + (y1c * ww + x0c) * NC);
        acc += w11 * __ldg(mem + (y1c * ww + x1c) * NC);
        e[s] = acc;
    }
    // store emb[c][s] (32B per channel, two 128-bit stores)
    *(float4*)&emb[tid * 8 + 0] = make_float4(e[0], e[1], e[2], e[3]);
    *(float4*)&emb[tid * 8 + 4] = make_float4(e[4], e[5], e[6], e[7]);
    __syncthreads();

    // ---- Stage 3: h = tanh(emb @ W1 + b1), thread = output channel j ----
    {
        const float* w1p = W1 + tid;  // column j, stride 256 over c (coalesced across j)
        const ulonglong2* eb = (const ulonglong2*)emb;
        uint64_t a01 = 0ull, a23 = 0ull, a45 = 0ull, a67 = 0ull;
#pragma unroll 8
        for (int c = 0; c < NC; ++c) {
            const float w = __ldg(w1p + c * NC);
            const uint64_t wp = pack2(w);
            const ulonglong2 eA = eb[2 * c + 0];   // emb[c][0..3] as 2x f32x2 (broadcast)
            const ulonglong2 eB = eb[2 * c + 1];   // emb[c][4..7]
            ffma2(a01, eA.x, wp);
            ffma2(a23, eA.y, wp);
            ffma2(a45, eB.x, wp);
            ffma2(a67, eB.y, wp);
        }
        const float bj = __ldg(b1 + tid);
        const float2 f01 = unpack2(a01), f23 = unpack2(a23);
        const float2 f45 = unpack2(a45), f67 = unpack2(a67);
        float hv[8] = {f01.x, f01.y, f23.x, f23.y, f45.x, f45.y, f67.x, f67.y};
#pragma unroll
        for (int s = 0; s < NS; ++s) hv[s] = tanh_fast(hv[s] + bj);
        *(float4*)&hsm[tid * 8 + 0] = make_float4(hv[0], hv[1], hv[2], hv[3]);
        *(float4*)&hsm[tid * 8 + 4] = make_float4(hv[4], hv[5], hv[6], hv[7]);
    }
    __syncthreads();

    // ---- Stage 4: off = S_SCALE*tanh(h @ W2 + b2); out = off + pts ----
    if (tid < 32) {
        const int s = tid >> 2;
        const int k = tid & 3;     // k = np*2 + xy
        float acc = __ldg(b2 + k);
#pragma unroll 8
        for (int j = 0; j < NC; ++j)
            acc = fmaf(hsm[j * 8 + s], w2s[j * 4 + k], acc);
        const float v = SSCALE * tanh_fast(acc) + pts[s * 2 + (k & 1)];
        out[bq * 32 + s * 4 + k] = v;
    }
}

extern "C" void kernel_launch(void* const* d_in, const int* in_sizes, int n_in,
                              void* d_out, int out_size) {
    const float* ref_polys  = (const float*)d_in[0];
    const int*   ref_levels = (const int*)  d_in[1];
    const float* memory     = (const float*)d_in[2];
    const float* W1         = (const float*)d_in[3];
    const float* b1         = (const float*)d_in[4];
    const float* W2         = (const float*)d_in[5];
    const float* b2         = (const float*)d_in[6];
    float* out = (float*)d_out;

    decoder_kernel<<<NB * NQ, 256>>>(ref_polys, ref_levels, memory,
                                     W1, b1, W2, b2, out);
}

// round 3
// speedup vs baseline: 1.1736x; 1.1736x over previous
#include <cuda_runtime.h>
#include <cstdint>

// Problem constants
namespace {
constexpr int NB = 8;
constexpr int NQ = 500;
constexpr int NC = 256;   // channels
constexpr int NS = 8;     // sampling points
constexpr float SSCALE = 0.077f;
}

__constant__ int c_hw[4] = {80, 40, 20, 10};          // square levels
__constant__ int c_st[4] = {0, 6400, 8000, 8400};

__device__ __forceinline__ float tanh_fast(float x) {
    float r;
    asm("tanh.approx.f32 %0, %1;" : "=f"(r) : "f"(x));
    return r;
}
__device__ __forceinline__ uint64_t pack2(float v) {
    uint64_t r;
    asm("mov.b64 %0, {%1, %1};" : "=l"(r) : "r"(__float_as_uint(v)));
    return r;
}
__device__ __forceinline__ uint64_t b64(float x, float y) {
    uint64_t r;
    asm("mov.b64 %0, {%1, %2};" : "=l"(r) : "f"(x), "f"(y));
    return r;
}
__device__ __forceinline__ void ffma2(uint64_t& d, uint64_t a, uint64_t b) {
    asm("fma.rn.f32x2 %0, %1, %2, %0;" : "+l"(d) : "l"(a), "l"(b));
}
__device__ __forceinline__ float2 unpack2(uint64_t v) {
    float2 f;
    asm("mov.b64 {%0, %1}, %2;" : "=f"(f.x), "=f"(f.y) : "l"(v));
    return f;
}

// Block = 4 queries, 256 threads (4 groups x 64). grid = 1000.
__global__ __launch_bounds__(256) void decoder_kernel(
    const float* __restrict__ ref_polys,   // (B,Q,8)
    const int*   __restrict__ ref_levels,  // (B,Q)
    const float* __restrict__ memory,      // (B,8500,256)
    const float* __restrict__ W1,          // (256,256)
    const float* __restrict__ b1,          // (256,)
    const float* __restrict__ W2,          // (256,4)
    const float* __restrict__ b2,          // (4,)
    float*       __restrict__ out)         // (B,Q,16,2)
{
    __shared__ float pts[4][NS * 2];       // sampling points per query
    __shared__ int   sidx[4][NS][4];       // prescaled corner offsets (incl. batch+level base)
    __shared__ float swt[4][NS][4];        // bilinear weights (zeroed when invalid)
    __shared__ float emb[4][NC * NS];      // 32KB: emb[c][s], later reused for h[j][s]
    __shared__ float w2s[NC * 4];          // W2 staged

    const int tid = threadIdx.x;
    const int bq0 = blockIdx.x * 4;

    // Stage W2 into smem
    ((float4*)w2s)[tid] = __ldg(&((const float4*)W2)[tid]);

    // ---- Stage 1: per (g,s): polynomial eval + bilinear setup (32 lanes) ----
    if (tid < 32) {
        const int g = tid >> 3;
        const int s = tid & 7;
        const int bq = bq0 + g;
        const int b  = bq / NQ;
        const float lam = s * (1.0f / 7.0f);
        const float* rp = ref_polys + bq * 8;
        float px = ((rp[0] * lam + rp[1]) * lam + rp[2]) * lam + rp[3];
        float py = ((rp[4] * lam + rp[5]) * lam + rp[6]) * lam + rp[7];
        px = 2.0f * (px - 0.5f);
        py = 2.0f * (py - 0.5f);
        pts[g][s * 2 + 0] = px;
        pts[g][s * 2 + 1] = py;

        const int lvl = ref_levels[bq];
        const int ww  = c_hw[lvl];
        const float gx = (px + 1.0f) * 0.5f * (float)ww - 0.5f;
        const float gy = (py + 1.0f) * 0.5f * (float)ww - 0.5f;
        const float x0f = floorf(gx), y0f = floorf(gy);
        const float wx1 = gx - x0f, wy1 = gy - y0f;
        const float wx0 = 1.0f - wx1, wy0 = 1.0f - wy1;
        const int x0 = (int)x0f, y0 = (int)y0f;
        const bool vx0 = (x0 >= 0) && (x0 < ww);
        const bool vx1 = (x0 >= -1) && (x0 < ww - 1);
        const bool vy0 = (y0 >= 0) && (y0 < ww);
        const bool vy1 = (y0 >= -1) && (y0 < ww - 1);
        const int x0c = min(max(x0, 0), ww - 1);
        const int x1c = min(max(x0 + 1, 0), ww - 1);
        const int y0c = min(max(y0, 0), ww - 1);
        const int y1c = min(max(y0 + 1, 0), ww - 1);
        swt[g][s][0] = (vx0 && vy0) ? wy0 * wx0 : 0.0f;
        swt[g][s][1] = (vx1 && vy0) ? wy0 * wx1 : 0.0f;
        swt[g][s][2] = (vx0 && vy1) ? wy1 * wx0 : 0.0f;
        swt[g][s][3] = (vx1 && vy1) ? wy1 * wx1 : 0.0f;
        const int base = b * 8500 + c_st[lvl];
        sidx[g][s][0] = (base + y0c * ww + x0c) * NC;
        sidx[g][s][1] = (base + y0c * ww + x1c) * NC;
        sidx[g][s][2] = (base + y1c * ww + x0c) * NC;
        sidx[g][s][3] = (base + y1c * ww + x1c) * NC;
    }
    __syncthreads();

    // ---- Stage 2: bilinear gather, thread = channel c, loop over 4 queries ----
    {
        const int c = tid;
#pragma unroll
        for (int g = 0; g < 4; ++g) {
            float e[NS];
#pragma unroll
            for (int s = 0; s < NS; ++s) {
                const int4   ii = *(const int4*)  sidx[g][s];
                const float4 wv = *(const float4*)swt[g][s];
                float acc;
                acc  = wv.x * __ldg(memory + ii.x + c);
                acc += wv.y * __ldg(memory + ii.y + c);
                acc += wv.z * __ldg(memory + ii.z + c);
                acc += wv.w * __ldg(memory + ii.w + c);
                e[s] = acc;
            }
            *(float4*)&emb[g][c * 8 + 0] = make_float4(e[0], e[1], e[2], e[3]);
            *(float4*)&emb[g][c * 8 + 4] = make_float4(e[4], e[5], e[6], e[7]);
        }
    }
    __syncthreads();

    // ---- Stage 3: h = tanh(emb @ W1 + b1). Thread handles j = 4t..4t+3 for its query ----
    const int t  = tid & 63;
    const int g3 = tid >> 6;
    uint64_t acc[NS][2];      // [s][j-pair]: (j0,j1) and (j2,j3)
#pragma unroll
    for (int s = 0; s < NS; ++s) { acc[s][0] = 0ull; acc[s][1] = 0ull; }

    const float4* w1v = (const float4*)W1 + t;        // row c at + c*64
    const float4* ev  = (const float4*)(emb[g3]);     // emb[c][0..3] at 2c, [4..7] at 2c+1
#pragma unroll 4
    for (int c = 0; c < NC; ++c) {
        const float4 w = __ldg(w1v + c * 64);          // W1[c][4t..4t+3]
        const uint64_t w01 = b64(w.x, w.y);
        const uint64_t w23 = b64(w.z, w.w);
        const float4 eA = ev[2 * c + 0];               // broadcast
        const float4 eB = ev[2 * c + 1];               // broadcast
        const float es[NS] = {eA.x, eA.y, eA.z, eA.w, eB.x, eB.y, eB.z, eB.w};
#pragma unroll
        for (int s = 0; s < NS; ++s) {
            const uint64_t ep = pack2(es[s]);
            ffma2(acc[s][0], ep, w01);
            ffma2(acc[s][1], ep, w23);
        }
    }
    const float4 bv = __ldg((const float4*)b1 + t);
    float h[4][NS];
#pragma unroll
    for (int s = 0; s < NS; ++s) {
        const float2 p0 = unpack2(acc[s][0]);
        const float2 p1 = unpack2(acc[s][1]);
        h[0][s] = tanh_fast(p0.x + bv.x);
        h[1][s] = tanh_fast(p0.y + bv.y);
        h[2][s] = tanh_fast(p1.x + bv.z);
        h[3][s] = tanh_fast(p1.y + bv.w);
    }
    __syncthreads();   // all emb reads complete before overwrite

    // write h[j][s] into the emb buffer
#pragma unroll
    for (int j = 0; j < 4; ++j) {
        *(float4*)&emb[g3][(4 * t + j) * 8 + 0] = make_float4(h[j][0], h[j][1], h[j][2], h[j][3]);
        *(float4*)&emb[g3][(4 * t + j) * 8 + 4] = make_float4(h[j][4], h[j][5], h[j][6], h[j][7]);
    }
    __syncthreads();

    // ---- Stage 4: off = S_SCALE*tanh(h @ W2 + b2); out = off + pts ----
    if (t < 32) {
        const int s = t >> 2;
        const int k = t & 3;           // k = np*2 + xy
        float a4 = __ldg(b2 + k);
#pragma unroll 8
        for (int j = 0; j < NC; ++j)
            a4 = fmaf(emb[g3][j * 8 + s], w2s[j * 4 + k], a4);
        const float v = SSCALE * tanh_fast(a4) + pts[g3][s * 2 + (k & 1)];
        out[(bq0 + g3) * 32 + s * 4 + k] = v;
    }
}

extern "C" void kernel_launch(void* const* d_in, const int* in_sizes, int n_in,
                              void* d_out, int out_size) {
    const float* ref_polys  = (const float*)d_in[0];
    const int*   ref_levels = (const int*)  d_in[1];
    const float* memory     = (const float*)d_in[2];
    const float* W1         = (const float*)d_in[3];
    const float* b1         = (const float*)d_in[4];
    const float* W2         = (const float*)d_in[5];
    const float* b2         = (const float*)d_in[6];
    float* out = (float*)d_out;

    decoder_kernel<<<(NB * NQ) / 4, 256>>>(ref_polys, ref_levels, memory,
                                           W1, b1, W2, b2, out);
}

// round 5
// speedup vs baseline: 3.1714x; 2.7024x over previous
#include <cuda_runtime.h>
#include <cstdint>

// ---------------- problem constants ----------------
namespace {
constexpr int NB = 8;
constexpr int NQ = 500;
constexpr int NC = 256;     // channels
constexpr int NS = 8;       // sampling points
constexpr float SSCALE = 0.077f;

constexpr int QB   = 8;               // queries per block
constexpr int ROWS = 64;              // QB * NS (GEMM M tile)
constexpr int KCH  = 64;              // K-chunk
constexpr int NCH  = NC / KCH;        // 4
constexpr int THREADS = 256;          // 8 warps

constexpr int ASTR = 68;              // A row stride (floats), 68 % 32 == 4 -> conflict-free frags
constexpr int BSTR = 264;             // B row stride (floats), 264 % 32 == 8 -> conflict-free frags

// dynamic smem byte offsets
constexpr int SM_A    = 0;            // 64 x 68 x 4  = 17408
constexpr int SM_B    = 17408;        // 64 x 264 x 4 = 67584
constexpr int SM_PTS  = 84992;        // 64 * 2 floats
constexpr int SM_IDX  = 85504;        // 64 * int4
constexpr int SM_WT   = 86528;        // 64 * float4
constexpr int SM_B1S  = 87552;        // 256 floats
constexpr int SM_W2S  = 88576;        // 256*4 floats
constexpr int SM_PART = 92672;        // 64*4 floats
constexpr int SMEM_TOTAL = 93696;     // ~91.5 KB -> 2 CTAs/SM
}

__constant__ int c_hw[4] = {80, 40, 20, 10};
__constant__ int c_st[4] = {0, 6400, 8000, 8400};

__device__ __forceinline__ float tanh_fast(float x) {
    float r; asm("tanh.approx.f32 %0, %1;" : "=f"(r) : "f"(x)); return r;
}

// m16n8k8 tf32 MMA (portable PTX, sm_80+): D = A*B + D, fp32 accumulate.
__device__ __forceinline__ void mma_tf32(float* c, const uint32_t* a, const uint32_t* b) {
    asm volatile(
        "mma.sync.aligned.m16n8k8.row.col.f32.tf32.tf32.f32 "
        "{%0,%1,%2,%3}, {%4,%5,%6,%7}, {%8,%9}, {%0,%1,%2,%3};"
        : "+f"(c[0]), "+f"(c[1]), "+f"(c[2]), "+f"(c[3])
        : "r"(a[0]), "r"(a[1]), "r"(a[2]), "r"(a[3]), "r"(b[0]), "r"(b[1]));
}

__global__ __launch_bounds__(THREADS, 2) void decoder_kernel(
    const float* __restrict__ ref_polys,   // (B,Q,8)
    const int*   __restrict__ ref_levels,  // (B,Q)
    const float* __restrict__ memory,      // (B,8500,256)
    const float* __restrict__ W1,          // (256,256)  rows = k, cols = n
    const float* __restrict__ b1,          // (256,)
    const float* __restrict__ W2,          // (256,4)
    const float* __restrict__ b2,          // (4,)
    float*       __restrict__ out)         // (B,Q,16,2)
{
    extern __shared__ char smem[];
    const int tid  = threadIdx.x;
    const int lane = tid & 31;
    const int wid  = tid >> 5;
    const int bq0  = blockIdx.x * QB;

    float* ptsS  = (float*)(smem + SM_PTS);
    float* b1s   = (float*)(smem + SM_B1S);
    float* w2s   = (float*)(smem + SM_W2S);
    float* part  = (float*)(smem + SM_PART);

    // ---- stage 1: bilinear setup per row (threads 0..63) ----
    if (tid < ROWS) {
        const int r = tid, g = r >> 3, s = r & 7;
        const int bq = bq0 + g;
        const int b  = bq / NQ;
        const float lam = s * (1.0f / 7.0f);
        const float* rp = ref_polys + bq * 8;
        float px = ((rp[0] * lam + rp[1]) * lam + rp[2]) * lam + rp[3];
        float py = ((rp[4] * lam + rp[5]) * lam + rp[6]) * lam + rp[7];
        px = 2.0f * (px - 0.5f);
        py = 2.0f * (py - 0.5f);
        ptsS[r * 2 + 0] = px;
        ptsS[r * 2 + 1] = py;

        const int lvl = ref_levels[bq];
        const int ww  = c_hw[lvl];
        const float gx = (px + 1.0f) * 0.5f * (float)ww - 0.5f;
        const float gy = (py + 1.0f) * 0.5f * (float)ww - 0.5f;
        const float x0f = floorf(gx), y0f = floorf(gy);
        const float wx1 = gx - x0f, wy1 = gy - y0f;
        const float wx0 = 1.0f - wx1, wy0 = 1.0f - wy1;
        const int x0 = (int)x0f, y0 = (int)y0f;
        const bool vx0 = (x0 >= 0) && (x0 < ww);
        const bool vx1 = (x0 >= -1) && (x0 < ww - 1);
        const bool vy0 = (y0 >= 0) && (y0 < ww);
        const bool vy1 = (y0 >= -1) && (y0 < ww - 1);
        const int x0c = min(max(x0, 0), ww - 1);
        const int x1c = min(max(x0 + 1, 0), ww - 1);
        const int y0c = min(max(y0, 0), ww - 1);
        const int y1c = min(max(y0 + 1, 0), ww - 1);
        const int base = b * 8500 + c_st[lvl];
        *(int4*)(smem + SM_IDX + r * 16) =
            make_int4((base + y0c * ww + x0c) * NC, (base + y0c * ww + x1c) * NC,
                      (base + y1c * ww + x0c) * NC, (base + y1c * ww + x1c) * NC);
        *(float4*)(smem + SM_WT + r * 16) =
            make_float4((vx0 && vy0) ? wy0 * wx0 : 0.0f, (vx1 && vy0) ? wy0 * wx1 : 0.0f,
                        (vx0 && vy1) ? wy1 * wx0 : 0.0f, (vx1 && vy1) ? wy1 * wx1 : 0.0f);
        ((float4*)part)[tid] = make_float4(0.f, 0.f, 0.f, 0.f);
    }
    b1s[tid] = b1[tid];
    ((float4*)w2s)[tid] = ((const float4*)W2)[tid];
    __syncthreads();

    // ---- warp tiling: warp owns M-half (mh) x N-quarter (nq) ----
    const int mh = wid & 1;            // 0/1 -> rows [0,32) / [32,64)
    const int nq = wid >> 1;           // 0..3 -> cols [64*nq, 64*nq+64)
    const int g  = lane >> 2;          // mma group id (0..7)
    const int tg = lane & 3;           // thread-in-group (0..3)

    float acc[2][8][4];
#pragma unroll
    for (int mt = 0; mt < 2; ++mt)
#pragma unroll
        for (int nt = 0; nt < 8; ++nt)
#pragma unroll
            for (int i = 0; i < 4; ++i) acc[mt][nt][i] = 0.f;

    const uint32_t* As = (const uint32_t*)(smem + SM_A);
    const uint32_t* Bs = (const uint32_t*)(smem + SM_B);

    for (int kc = 0; kc < NCH; ++kc) {
        const int c0 = kc * KCH;

        // -- fill A chunk (gather): warp wid handles rows [wid*8, wid*8+8) --
        {
            const int rg = wid * 8;
#pragma unroll
            for (int i = 0; i < 8; ++i) {
                const int r = rg + i;
                const int4   ii = *(const int4*)(smem + SM_IDX + r * 16);
                const float4 wv = *(const float4*)(smem + SM_WT + r * 16);
#pragma unroll
                for (int kh = 0; kh < 2; ++kh) {
                    const int cc = c0 + kh * 32 + lane;
                    float a;
                    a  = wv.x * __ldg(memory + ii.x + cc);
                    a += wv.y * __ldg(memory + ii.y + cc);
                    a += wv.z * __ldg(memory + ii.z + cc);
                    a += wv.w * __ldg(memory + ii.w + cc);
                    ((float*)(smem + SM_A))[r * ASTR + kh * 32 + lane] = a;
                }
            }
        }
        // -- fill B chunk: B[k][j] = W1[c0+k][j], 16 float4 per thread --
        {
            const float4* w14 = (const float4*)(W1 + c0 * NC);
#pragma unroll
            for (int i = 0; i < 16; ++i) {
                const int fi   = tid + i * 256;       // 0..4095
                const int row  = fi >> 6;
                const int col4 = fi & 63;
                const float4 f = __ldg(w14 + row * 64 + col4);
                *(float4*)(smem + SM_B + row * (BSTR * 4) + col4 * 16) = f;
            }
        }
        __syncthreads();

        // -- MMA over this chunk: 8 k-steps of k8 --
#pragma unroll 2
        for (int ks = 0; ks < 8; ++ks) {
            const int k0 = ks * 8;
            uint32_t a[2][4];
#pragma unroll
            for (int mt = 0; mt < 2; ++mt) {
                const int rb = mh * 32 + mt * 16;
                a[mt][0] = As[(rb + g)     * ASTR + k0 + tg];
                a[mt][1] = As[(rb + g + 8) * ASTR + k0 + tg];
                a[mt][2] = As[(rb + g)     * ASTR + k0 + tg + 4];
                a[mt][3] = As[(rb + g + 8) * ASTR + k0 + tg + 4];
            }
            uint32_t b[8][2];
#pragma unroll
            for (int nt = 0; nt < 8; ++nt) {
                const int jb = nq * 64 + nt * 8 + g;
                b[nt][0] = Bs[(k0 + tg)     * BSTR + jb];
                b[nt][1] = Bs[(k0 + tg + 4) * BSTR + jb];
            }
#pragma unroll
            for (int mt = 0; mt < 2; ++mt)
#pragma unroll
                for (int nt = 0; nt < 8; ++nt)
                    mma_tf32(acc[mt][nt], a[mt], b[nt]);
        }
        __syncthreads();   // protect A/B before next chunk refill
    }

    // ---- epilogue: h = tanh(v + b1); layer-2 partials; reduce ----
    float p[2][2][4];      // [mt][row-half(+0/+8)][k]
#pragma unroll
    for (int mt = 0; mt < 2; ++mt)
#pragma unroll
        for (int rh = 0; rh < 2; ++rh)
#pragma unroll
            for (int k = 0; k < 4; ++k) p[mt][rh][k] = 0.f;

#pragma unroll
    for (int mt = 0; mt < 2; ++mt) {
#pragma unroll
        for (int nt = 0; nt < 8; ++nt) {
            const int cb = nq * 64 + nt * 8 + 2 * tg;
#pragma unroll
            for (int v = 0; v < 4; ++v) {
                const int rh  = v >> 1;            // c0,c1 -> row+0 ; c2,c3 -> row+8
                const int col = cb + (v & 1);
                const float hv = tanh_fast(acc[mt][nt][v] + b1s[col]);
                const float4 w2v = *(const float4*)(w2s + col * 4);
                p[mt][rh][0] = fmaf(hv, w2v.x, p[mt][rh][0]);
                p[mt][rh][1] = fmaf(hv, w2v.y, p[mt][rh][1]);
                p[mt][rh][2] = fmaf(hv, w2v.z, p[mt][rh][2]);
                p[mt][rh][3] = fmaf(hv, w2v.w, p[mt][rh][3]);
            }
        }
    }
    // reduce over tg (4 lanes hold disjoint col sets of the same row)
#pragma unroll
    for (int mt = 0; mt < 2; ++mt)
#pragma unroll
        for (int rh = 0; rh < 2; ++rh)
#pragma unroll
            for (int k = 0; k < 4; ++k) {
                float v = p[mt][rh][k];
                v += __shfl_xor_sync(0xFFFFFFFFu, v, 1);
                v += __shfl_xor_sync(0xFFFFFFFFu, v, 2);
                if (tg == 0) {
                    const int row = mh * 32 + mt * 16 + rh * 8 + g;
                    atomicAdd(&part[row * 4 + k], v);   // 4 n-quarter warps sum here
                }
            }
    __syncthreads();

    // ---- final: off = S*tanh(part + b2) + pts ----
    if (tid < ROWS) {
        const int r = tid, gq = r >> 3, s = r & 7;
        const float px = ptsS[r * 2 + 0];
        const float py = ptsS[r * 2 + 1];
        float* o = out + (size_t)(bq0 + gq) * 32 + s * 4;
#pragma unroll
        for (int k = 0; k < 4; ++k) {
            const float logit = part[r * 4 + k] + __ldg(b2 + k);
            o[k] = SSCALE * tanh_fast(logit) + ((k & 1) ? py : px);
        }
    }
}

extern "C" void kernel_launch(void* const* d_in, const int* in_sizes, int n_in,
                              void* d_out, int out_size) {
    const float* ref_polys  = (const float*)d_in[0];
    const int*   ref_levels = (const int*)  d_in[1];
    const float* memory     = (const float*)d_in[2];
    const float* W1         = (const float*)d_in[3];
    const float* b1         = (const float*)d_in[4];
    const float* W2         = (const float*)d_in[5];
    const float* b2         = (const float*)d_in[6];
    float* out = (float*)d_out;

    static int configured = 0;
    if (!configured) {
        cudaFuncSetAttribute(decoder_kernel,
                             cudaFuncAttributeMaxDynamicSharedMemorySize, SMEM_TOTAL);
        configured = 1;
    }
    decoder_kernel<<<(NB * NQ) / QB, THREADS, SMEM_TOTAL>>>(
        ref_polys, ref_levels, memory, W1, b1, W2, b2, out);
}